// round 7
// baseline (speedup 1.0000x reference)
#include <cuda_runtime.h>
#include <cuda_fp16.h>
#include <stdint.h>

// Shapes (fixed): x [B=256, N=196, C=768], weight [C=768, N=196], y [B, N, C]
#define NREAL  196
#define CDIM   768
#define KC     208        // contraction pad (n positions), 13 k-steps
#define KF     224        // DCT-frequency (free) pad -> 4 N-groups of 56
#define KSTEPS 13
#define MC     128        // channels per tile
#define NTILES 1536       // 256 batches * 6 channel-blocks
#define GRID   148        // persistent
#define NTHREADS 512      // 16 warps: 4 M-groups x 4 N-groups

#define XPITCHB 272       // X row pitch bytes (136 halfs; 272/16=17 odd -> conflict-free)
#define TPITCHB 464       // T row pitch bytes (232 halfs; 464/16=29 odd -> conflict-free)
#define BPITCH  232       // B1 pitch halfs (464B)
#define WPITCH  224

#define SM_B1  0                      // 224*232*2 = 103,936
#define SM_P0  103936                 // 59,392 (X: 208x136 halfs; T: 128x232 halfs)
#define SM_P1  163328                 // 59,392
#define PBYTES 59392
#define SMEM_TOTAL 222720             // <= 232,448
#define NF4    6272                   // float4 per X tile (196 rows * 32)

__device__ __align__(16) __half g_B1[KF * BPITCH];     // B1[n][k] = 2*cos(pi*k*(2n+1)/(2N)), 0-pad
__device__ __align__(16) __half g_wh2[CDIM * WPITCH];  // w[c][k] * s_k, zero-padded

// ---------------- helpers ----------------
__device__ __forceinline__ uint32_t smem_u32(const void* p) {
    uint32_t a;
    asm("{ .reg .u64 t; cvta.to.shared.u64 t, %1; cvt.u32.u64 %0, t; }" : "=r"(a) : "l"(p));
    return a;
}
__device__ __forceinline__ void ldsm_x4(uint32_t addr, uint32_t& r0, uint32_t& r1,
                                        uint32_t& r2, uint32_t& r3) {
    asm volatile("ldmatrix.sync.aligned.m8n8.x4.shared.b16 {%0,%1,%2,%3}, [%4];"
                 : "=r"(r0), "=r"(r1), "=r"(r2), "=r"(r3) : "r"(addr));
}
__device__ __forceinline__ void ldsm_x2(uint32_t addr, uint32_t& r0, uint32_t& r1) {
    asm volatile("ldmatrix.sync.aligned.m8n8.x2.shared.b16 {%0,%1}, [%2];"
                 : "=r"(r0), "=r"(r1) : "r"(addr));
}
__device__ __forceinline__ void ldsm_x4t(uint32_t addr, uint32_t& r0, uint32_t& r1,
                                         uint32_t& r2, uint32_t& r3) {
    asm volatile("ldmatrix.sync.aligned.m8n8.x4.trans.shared.b16 {%0,%1,%2,%3}, [%4];"
                 : "=r"(r0), "=r"(r1), "=r"(r2), "=r"(r3) : "r"(addr));
}
__device__ __forceinline__ void ldsm_x2t(uint32_t addr, uint32_t& r0, uint32_t& r1) {
    asm volatile("ldmatrix.sync.aligned.m8n8.x2.trans.shared.b16 {%0,%1}, [%2];"
                 : "=r"(r0), "=r"(r1) : "r"(addr));
}
__device__ __forceinline__ void mma16816(float c[4], uint32_t a0, uint32_t a1, uint32_t a2,
                                         uint32_t a3, uint32_t b0, uint32_t b1) {
    asm volatile(
        "mma.sync.aligned.m16n8k16.row.col.f32.f16.f16.f32 "
        "{%0,%1,%2,%3}, {%4,%5,%6,%7}, {%8,%9}, {%0,%1,%2,%3};"
        : "+f"(c[0]), "+f"(c[1]), "+f"(c[2]), "+f"(c[3])
        : "r"(a0), "r"(a1), "r"(a2), "r"(a3), "r"(b0), "r"(b1));
}
__device__ __forceinline__ void xstore(char* dst, int pfi, float4 v) {
    __half2 h0 = __floats2half2_rn(v.x, v.y);
    __half2 h1 = __floats2half2_rn(v.z, v.w);
    uint2 u = make_uint2(*(uint32_t*)&h0, *(uint32_t*)&h1);
    *(uint2*)(dst + (pfi >> 5) * XPITCHB + (pfi & 31) * 8) = u;
}

// ---------------- fused setup ----------------
__global__ void setup_all(const float* __restrict__ w) {
    int r = blockIdx.x;    // 0..767
    int k = threadIdx.x;   // 0..231
    if (k < WPITCH) {
        float s = (k == 0) ? (0.25f / NREAL) : ((k < NREAL) ? (0.5f / NREAL) : 0.f);
        float wv = (k < NREAL) ? w[(size_t)r * NREAL + k] : 0.f;
        g_wh2[r * WPITCH + k] = __float2half_rn(wv * s);
    }
    if (r < KF) {
        float v = 0.f;
        if (r < NREAL && k < NREAL) {
            int rr = (k * (2 * r + 1)) % (4 * NREAL);
            v = 2.f * cospif((float)rr / (float)(2 * NREAL));
        }
        g_B1[r * BPITCH + k] = __float2half_rn(v);
    }
}

// ---------------- main persistent kernel ----------------
__global__ __launch_bounds__(NTHREADS, 1)
void dct_mma_kernel(const float* __restrict__ x, float* __restrict__ y) {
    extern __shared__ __align__(16) char smem[];
    const uint32_t sb = smem_u32(smem);
    const uint32_t sB = sb + SM_B1;
    const int tid = threadIdx.x;
    const int lane = tid & 31, wid = tid >> 5;
    const int mw = wid & 3;              // 4 M-groups of 32 channels
    const int nw = wid >> 2;             // 4 N-groups of 56
    const int cw = mw * 32;
    const int nbase = nw * 56;

    const int lr  = lane & 15;
    const int lc  = lane >> 4;
    const int kk  = (lane & 7) + ((lane >> 4) << 3);
    const int g8  = ((lane >> 3) & 1) << 3;
    const int grp = lane >> 2;
    const int q2  = (lane & 3) << 1;

    // One-time: copy B1, zero both P buffers (incl. X pad rows).
    {
        const float4* s1 = (const float4*)g_B1;
        float4* d1 = (float4*)(smem + SM_B1);
        for (int i = tid; i < (KF * BPITCH * 2) / 16; i += NTHREADS) d1[i] = s1[i];
        float4 z = make_float4(0.f, 0.f, 0.f, 0.f);
        float4* pz = (float4*)(smem + SM_P0);
        for (int i = tid; i < (2 * PBYTES) / 16; i += NTHREADS) pz[i] = z;
    }

    // Prologue: blocking load of first tile into P0.
    int t = blockIdx.x;
    __syncthreads();
    {
        const float4* xp = (const float4*)(x + (size_t)(t / 6) * NREAL * CDIM + (t % 6) * MC);
        char* dst = smem + SM_P0;
        for (int i = tid; i < NF4; i += NTHREADS)
            xstore(dst, i, xp[(i >> 5) * (CDIM / 4) + (i & 31)]);
    }
    __syncthreads();

    int it = 0;
    for (; t < NTILES; t += GRID, it ^= 1) {
        const int c0 = (t % 6) * MC;
        const int b  = t / 6;
        char* Pa = smem + (it ? SM_P1 : SM_P0);
        char* Pb = smem + (it ? SM_P0 : SM_P1);
        const uint32_t sPa = sb + (it ? SM_P1 : SM_P0);

        const int t2 = t + GRID;
        const bool pfv = (t2 < NTILES);
        const float4* pfsrc = (const float4*)(x +
            (size_t)((pfv ? t2 : 0) / 6) * NREAL * CDIM + ((pfv ? t2 : 0) % 6) * MC);

        // Re-zero Pb's X pad rows (T of the tile before last clobbered them).
        if (pfv) {
            unsigned long long* pz = (unsigned long long*)(Pb + NREAL * XPITCHB);
            for (int i = tid; i < (KC - NREAL) * XPITCHB / 8; i += NTHREADS) pz[i] = 0ull;
        }

        float acc[2][7][4];
        #pragma unroll
        for (int mt = 0; mt < 2; mt++)
            #pragma unroll
            for (int nt = 0; nt < 7; nt++)
                #pragma unroll
                for (int j = 0; j < 4; j++) acc[mt][nt][j] = 0.f;

        // ---- GEMM1: C1[c][kdct] = X^T x B1 (trans A from X[n][c]); prefetch next X ----
        {
            const uint32_t aB  = sPa + (uint32_t)(kk * XPITCHB) + (uint32_t)((cw + g8) * 2);
            const uint32_t bB  = sB + (uint32_t)(lr * (BPITCH * 2)) + (uint32_t)((nbase + lc * 8) * 2);
            const uint32_t bB2 = sB + (uint32_t)(lr * (BPITCH * 2)) + (uint32_t)((nbase + 48) * 2);
            #pragma unroll 1
            for (int ks = 0; ks < KSTEPS; ks++) {
                const int pfi = ks * NTHREADS + tid;   // 13*512 >= 6272: all loads here
                const bool ld = pfv && (pfi < NF4);
                float4 v;
                if (ld) v = pfsrc[(pfi >> 5) * (CDIM / 4) + (pfi & 31)];

                const uint32_t kro = (uint32_t)(ks * 16 * XPITCHB);
                const uint32_t krb = (uint32_t)(ks * 16 * (BPITCH * 2));
                uint32_t a[2][4];
                #pragma unroll
                for (int mt = 0; mt < 2; mt++)
                    ldsm_x4t(aB + kro + (uint32_t)(mt * 32),
                             a[mt][0], a[mt][1], a[mt][2], a[mt][3]);
                uint32_t bf[7][2];
                #pragma unroll
                for (int p = 0; p < 3; p++)
                    ldsm_x4t(bB + krb + (uint32_t)(p * 32),
                             bf[2 * p][0], bf[2 * p][1], bf[2 * p + 1][0], bf[2 * p + 1][1]);
                ldsm_x2t(bB2 + krb, bf[6][0], bf[6][1]);
                #pragma unroll
                for (int mt = 0; mt < 2; mt++)
                    #pragma unroll
                    for (int nt = 0; nt < 7; nt++)
                        mma16816(acc[mt][nt], a[mt][0], a[mt][1], a[mt][2], a[mt][3],
                                 bf[nt][0], bf[nt][1]);

                if (ld) xstore(Pb, pfi, v);
            }
        }
        __syncthreads();

        // ---- mid: T[c][k] = fp16( C1 * g_wh2[c][k] ), T in Pa (pitch 464B) ----
        #pragma unroll
        for (int mt = 0; mt < 2; mt++) {
            const int r0 = cw + mt * 16 + grp;
            const int r1 = r0 + 8;
            #pragma unroll
            for (int nt = 0; nt < 7; nt++) {
                const int col = nbase + nt * 8 + q2;
                float2 w0 = __half22float2(*(const __half2*)&g_wh2[(c0 + r0) * WPITCH + col]);
                float2 w1 = __half22float2(*(const __half2*)&g_wh2[(c0 + r1) * WPITCH + col]);
                __half2 h0 = __floats2half2_rn(acc[mt][nt][0] * w0.x, acc[mt][nt][1] * w0.y);
                __half2 h1 = __floats2half2_rn(acc[mt][nt][2] * w1.x, acc[mt][nt][3] * w1.y);
                *(uint32_t*)(Pa + r0 * TPITCHB + col * 2) = *(uint32_t*)&h0;
                *(uint32_t*)(Pa + r1 * TPITCHB + col * 2) = *(uint32_t*)&h1;
            }
        }
        __syncthreads();

        #pragma unroll
        for (int mt = 0; mt < 2; mt++)
            #pragma unroll
            for (int nt = 0; nt < 7; nt++)
                #pragma unroll
                for (int j = 0; j < 4; j++) acc[mt][nt][j] = 0.f;

        // ---- GEMM2: C2[c][n] = T x B1^T (non-trans A,B); k>=208 contributions are zero ----
        {
            const uint32_t aB  = sPa + (uint32_t)((cw + lr) * TPITCHB) + (uint32_t)(lc * 16);
            const uint32_t bB  = sB + (uint32_t)((nbase + kk) * (BPITCH * 2)) + (uint32_t)(g8 * 2);
            const uint32_t bB2 = sB + (uint32_t)((nbase + 48 + (lane & 7)) * (BPITCH * 2)) +
                                 (uint32_t)(g8 * 2);
            #pragma unroll 1
            for (int ks = 0; ks < KSTEPS; ks++) {
                const uint32_t ko = (uint32_t)(ks * 32);
                uint32_t a[2][4];
                #pragma unroll
                for (int mt = 0; mt < 2; mt++)
                    ldsm_x4(aB + (uint32_t)(mt * 16 * TPITCHB) + ko,
                            a[mt][0], a[mt][1], a[mt][2], a[mt][3]);
                uint32_t bf[7][2];
                #pragma unroll
                for (int p = 0; p < 3; p++)
                    ldsm_x4(bB + (uint32_t)(p * 16 * (BPITCH * 2)) + ko,
                            bf[2 * p][0], bf[2 * p][1], bf[2 * p + 1][0], bf[2 * p + 1][1]);
                ldsm_x2(bB2 + ko, bf[6][0], bf[6][1]);
                #pragma unroll
                for (int mt = 0; mt < 2; mt++)
                    #pragma unroll
                    for (int nt = 0; nt < 7; nt++)
                        mma16816(acc[mt][nt], a[mt][0], a[mt][1], a[mt][2], a[mt][3],
                                 bf[nt][0], bf[nt][1]);
            }
        }

        // ---- epilogue: y[b, n, c0 + c] = C2[c][n] ----
        {
            float* yb = y + (size_t)b * NREAL * CDIM + c0;
            #pragma unroll
            for (int mt = 0; mt < 2; mt++) {
                const int r0 = cw + mt * 16 + grp;
                const int r1 = r0 + 8;
                #pragma unroll
                for (int nt = 0; nt < 7; nt++) {
                    const int ncol = nbase + nt * 8 + q2;
                    if (ncol < NREAL) {
                        yb[(size_t)ncol * CDIM + r0]       = acc[mt][nt][0];
                        yb[(size_t)(ncol + 1) * CDIM + r0] = acc[mt][nt][1];
                        yb[(size_t)ncol * CDIM + r1]       = acc[mt][nt][2];
                        yb[(size_t)(ncol + 1) * CDIM + r1] = acc[mt][nt][3];
                    }
                }
            }
        }
        __syncthreads();   // T reads + prefetch stores complete before next tile
    }
}

extern "C" void kernel_launch(void* const* d_in, const int* in_sizes, int n_in,
                              void* d_out, int out_size) {
    const float* x = (const float*)d_in[0];  // [B, N, C] fp32
    const float* w = (const float*)d_in[1];  // [C, N]    fp32
    float* y = (float*)d_out;                // [B, N, C] fp32

    cudaFuncSetAttribute(dct_mma_kernel,
                         cudaFuncAttributeMaxDynamicSharedMemorySize, SMEM_TOTAL);

    setup_all<<<CDIM, BPITCH>>>(w);
    dct_mma_kernel<<<GRID, NTHREADS, SMEM_TOTAL>>>(x, y);
}

// round 10
// speedup vs baseline: 1.3605x; 1.3605x over previous
#include <cuda_runtime.h>
#include <cuda_fp16.h>
#include <stdint.h>

// Shapes (fixed): x [B=256, N=196, C=768], weight [C=768, N=196], y [B, N, C]
// Even/odd DCT folding: 98-point half-transforms, padded to 112 (7 k-steps).
#define NREAL  196
#define HALFN  98
#define CDIM   768
#define KH     112        // half-dim padded (7*16)
#define KSTEPS 7
#define MC     128        // channels per tile
#define NTILES 1536       // 256 batches * 6 channel-blocks
#define GRID   148        // persistent
#define NTHREADS 512      // 16 warps: 4 M x {even,odd} x 2 N-groups

#define XPITCHB 272       // X row pitch bytes (136 halfs; /16 odd -> conflict-free)
#define TPITCHB 240       // T/Y row pitch bytes (120 halfs; /16 odd -> conflict-free)
#define BPITCHB 240       // B half-matrix pitch bytes
#define WPITCH  224       // folded weight pitch (112 even | 112 odd)

#define SM_B1E 0                       // 112*240 = 26,880
#define SM_B1O 26880                   // 26,880
#define SM_P0  53760                   // 61,440 (X: 224x272B; or Te/To,Ye/Yo: 2x128x240B)
#define SM_P1  115200                  // 61,440
#define PBYTES 61440
#define TOFF   30720                   // odd-half offset within T/Y region
#define SMEM_TOTAL 176640
#define NPAIR4 3136                    // pair-tasks per tile: 98 rows * 32 float4

__device__ __align__(16) __half g_B1e[KH * 120];      // 2*cos(pi*(2j)*(2n+1)/(2N)), 0-pad
__device__ __align__(16) __half g_B1o[KH * 120];      // 2*cos(pi*(2j+1)*(2n+1)/(2N)), 0-pad
__device__ __align__(16) __half g_wf[CDIM * WPITCH];  // w[c][f]*s_f in folded order, 0-pad

// ---------------- helpers ----------------
__device__ __forceinline__ uint32_t smem_u32(const void* p) {
    uint32_t a;
    asm("{ .reg .u64 t; cvta.to.shared.u64 t, %1; cvt.u32.u64 %0, t; }" : "=r"(a) : "l"(p));
    return a;
}
__device__ __forceinline__ void ldsm_x4(uint32_t addr, uint32_t& r0, uint32_t& r1,
                                        uint32_t& r2, uint32_t& r3) {
    asm volatile("ldmatrix.sync.aligned.m8n8.x4.shared.b16 {%0,%1,%2,%3}, [%4];"
                 : "=r"(r0), "=r"(r1), "=r"(r2), "=r"(r3) : "r"(addr));
}
__device__ __forceinline__ void ldsm_x2(uint32_t addr, uint32_t& r0, uint32_t& r1) {
    asm volatile("ldmatrix.sync.aligned.m8n8.x2.shared.b16 {%0,%1}, [%2];"
                 : "=r"(r0), "=r"(r1) : "r"(addr));
}
__device__ __forceinline__ void ldsm_x4t(uint32_t addr, uint32_t& r0, uint32_t& r1,
                                         uint32_t& r2, uint32_t& r3) {
    asm volatile("ldmatrix.sync.aligned.m8n8.x4.trans.shared.b16 {%0,%1,%2,%3}, [%4];"
                 : "=r"(r0), "=r"(r1), "=r"(r2), "=r"(r3) : "r"(addr));
}
__device__ __forceinline__ void ldsm_x2t(uint32_t addr, uint32_t& r0, uint32_t& r1) {
    asm volatile("ldmatrix.sync.aligned.m8n8.x2.trans.shared.b16 {%0,%1}, [%2];"
                 : "=r"(r0), "=r"(r1) : "r"(addr));
}
__device__ __forceinline__ void mma16816(float c[4], uint32_t a0, uint32_t a1, uint32_t a2,
                                         uint32_t a3, uint32_t b0, uint32_t b1) {
    asm volatile(
        "mma.sync.aligned.m16n8k16.row.col.f32.f16.f16.f32 "
        "{%0,%1,%2,%3}, {%4,%5,%6,%7}, {%8,%9}, {%0,%1,%2,%3};"
        : "+f"(c[0]), "+f"(c[1]), "+f"(c[2]), "+f"(c[3])
        : "r"(a0), "r"(a1), "r"(a2), "r"(a3), "r"(b0), "r"(b1));
}
// Fold pair (row n', row 195-n') -> E row n', O row 112+n'.
// Byte offset within row: task (pfi&31) covers 4 fp16 channels = 8 bytes.
__device__ __forceinline__ void foldstore(char* dst, int pfi, float4 va, float4 vb) {
    int n = pfi >> 5;
    int cb = (pfi & 31) * 8;   // BYTE offset (bug fixed: was *16)
    __half2 e0 = __floats2half2_rn(va.x + vb.x, va.y + vb.y);
    __half2 e1 = __floats2half2_rn(va.z + vb.z, va.w + vb.w);
    __half2 o0 = __floats2half2_rn(va.x - vb.x, va.y - vb.y);
    __half2 o1 = __floats2half2_rn(va.z - vb.z, va.w - vb.w);
    *(uint2*)(dst + n * XPITCHB + cb) =
        make_uint2(*(uint32_t*)&e0, *(uint32_t*)&e1);
    *(uint2*)(dst + (112 + n) * XPITCHB + cb) =
        make_uint2(*(uint32_t*)&o0, *(uint32_t*)&o1);
}

// ---------------- fused setup ----------------
__global__ void setup_all(const float* __restrict__ w) {
    int r = blockIdx.x;    // 0..767
    int k = threadIdx.x;   // 0..239
    if (k < WPITCH) {
        int sub = k / KH;               // 0 = even, 1 = odd
        int j = k - sub * KH;
        int f = 2 * j + sub;            // real frequency
        float v = 0.f;
        if (j < HALFN) {
            float s = (f == 0) ? (0.25f / NREAL) : (0.5f / NREAL);
            v = w[(size_t)r * NREAL + f] * s;
        }
        g_wf[r * WPITCH + k] = __float2half_rn(v);
    }
    if (r < KH && k < 120) {
        float ve = 0.f, vo = 0.f;
        if (r < HALFN && k < HALFN) {
            int re = ((2 * k) * (2 * r + 1)) % (4 * NREAL);
            int ro = ((2 * k + 1) * (2 * r + 1)) % (4 * NREAL);
            ve = 2.f * cospif((float)re / (float)(2 * NREAL));
            vo = 2.f * cospif((float)ro / (float)(2 * NREAL));
        }
        g_B1e[r * 120 + k] = __float2half_rn(ve);
        g_B1o[r * 120 + k] = __float2half_rn(vo);
    }
}

// ---------------- main persistent kernel ----------------
__global__ __launch_bounds__(NTHREADS, 1)
void dct_mma_kernel(const float* __restrict__ x, float* __restrict__ y) {
    extern __shared__ __align__(16) char smem[];
    const uint32_t sb = smem_u32(smem);
    const int tid = threadIdx.x;
    const int lane = tid & 31, wid = tid >> 5;
    const int mw = wid & 3;              // 4 M-groups of 32 channels
    const int nw = wid >> 2;
    const int sub = nw >> 1;             // 0 = even half, 1 = odd half
    const int ng = nw & 1;               // 2 N-groups of 56
    const int cw = mw * 32;
    const int nbase = ng * 56;
    const uint32_t sBm = sb + (sub ? SM_B1O : SM_B1E);

    const int lr  = lane & 15;
    const int lc  = lane >> 4;
    const int kk  = (lane & 7) + ((lane >> 4) << 3);
    const int g8  = ((lane >> 3) & 1) << 3;
    const int grp = lane >> 2;
    const int q2  = (lane & 3) << 1;

    // One-time: copy B matrices, zero both P buffers (incl. all pad rows).
    {
        const float4* s1 = (const float4*)g_B1e;
        const float4* s2 = (const float4*)g_B1o;
        float4* d1 = (float4*)(smem + SM_B1E);
        float4* d2 = (float4*)(smem + SM_B1O);
        for (int i = tid; i < (KH * 240) / 16; i += NTHREADS) { d1[i] = s1[i]; d2[i] = s2[i]; }
        float4 z = make_float4(0.f, 0.f, 0.f, 0.f);
        float4* pz = (float4*)(smem + SM_P0);
        for (int i = tid; i < (2 * PBYTES) / 16; i += NTHREADS) pz[i] = z;
    }

    // Prologue: blocking folded load of first tile into P0.
    int t = blockIdx.x;
    __syncthreads();
    {
        const float4* xp = (const float4*)(x + (size_t)(t / 6) * NREAL * CDIM + (t % 6) * MC);
        char* dst = smem + SM_P0;
        for (int i = tid; i < NPAIR4; i += NTHREADS) {
            int n = i >> 5, c4 = i & 31;
            float4 va = xp[n * (CDIM / 4) + c4];
            float4 vb = xp[(NREAL - 1 - n) * (CDIM / 4) + c4];
            foldstore(dst, i, va, vb);
        }
    }
    __syncthreads();

    int it = 0;
    for (; t < NTILES; t += GRID, it ^= 1) {
        const int c0 = (t % 6) * MC;
        const int b  = t / 6;
        char* Pa = smem + (it ? SM_P1 : SM_P0);
        char* Pb = smem + (it ? SM_P0 : SM_P1);
        const uint32_t sPa = sb + (it ? SM_P1 : SM_P0);

        const int t2 = t + GRID;
        const bool pfv = (t2 < NTILES);
        const float4* pfsrc = (const float4*)(x +
            (size_t)((pfv ? t2 : 0) / 6) * NREAL * CDIM + ((pfv ? t2 : 0) % 6) * MC);

        // Re-zero Pb's E/O pad rows (98..111, 210..223) — T/Y of an older tile dirtied them.
        if (pfv) {
            unsigned long long* z1 = (unsigned long long*)(Pb + HALFN * XPITCHB);
            unsigned long long* z2 = (unsigned long long*)(Pb + (112 + HALFN) * XPITCHB);
            for (int i = tid; i < (KH - HALFN) * XPITCHB / 8; i += NTHREADS) {
                z1[i] = 0ull; z2[i] = 0ull;
            }
        }

        float acc[2][7][4];
        #pragma unroll
        for (int mt = 0; mt < 2; mt++)
            #pragma unroll
            for (int nt = 0; nt < 7; nt++)
                #pragma unroll
                for (int j = 0; j < 4; j++) acc[mt][nt][j] = 0.f;

        // ---- GEMM1: C1[c][j] = (E|O)^T x B1(e|o); folded prefetch of next tile ----
        {
            const uint32_t aB  = sPa + (uint32_t)(sub * 112 * XPITCHB) +
                                 (uint32_t)(kk * XPITCHB) + (uint32_t)((cw + g8) * 2);
            const uint32_t bB  = sBm + (uint32_t)(lr * BPITCHB) + (uint32_t)((nbase + lc * 8) * 2);
            const uint32_t bB2 = sBm + (uint32_t)(lr * BPITCHB) + (uint32_t)((nbase + 48) * 2);
            #pragma unroll 1
            for (int ks = 0; ks < KSTEPS; ks++) {
                const int pfi = ks * NTHREADS + tid;   // 7*512 >= 3136: all pair-loads here
                const bool ld = pfv && (pfi < NPAIR4);
                float4 va, vb;
                if (ld) {
                    int n = pfi >> 5, c4 = pfi & 31;
                    va = pfsrc[n * (CDIM / 4) + c4];
                    vb = pfsrc[(NREAL - 1 - n) * (CDIM / 4) + c4];
                }

                const uint32_t kro = (uint32_t)(ks * 16 * XPITCHB);
                const uint32_t krb = (uint32_t)(ks * 16 * BPITCHB);
                uint32_t a[2][4];
                #pragma unroll
                for (int mt = 0; mt < 2; mt++)
                    ldsm_x4t(aB + kro + (uint32_t)(mt * 32),
                             a[mt][0], a[mt][1], a[mt][2], a[mt][3]);
                uint32_t bf[7][2];
                #pragma unroll
                for (int p = 0; p < 3; p++)
                    ldsm_x4t(bB + krb + (uint32_t)(p * 32),
                             bf[2 * p][0], bf[2 * p][1], bf[2 * p + 1][0], bf[2 * p + 1][1]);
                ldsm_x2t(bB2 + krb, bf[6][0], bf[6][1]);
                #pragma unroll
                for (int mt = 0; mt < 2; mt++)
                    #pragma unroll
                    for (int nt = 0; nt < 7; nt++)
                        mma16816(acc[mt][nt], a[mt][0], a[mt][1], a[mt][2], a[mt][3],
                                 bf[nt][0], bf[nt][1]);

                if (ld) foldstore(Pb, pfi, va, vb);
            }
        }
        __syncthreads();

        // ---- mid: T(e|o)[c][j] = fp16( C1 * g_wf[c][sub*112+j] ), over Pa ----
        #pragma unroll
        for (int mt = 0; mt < 2; mt++) {
            const int r0 = cw + mt * 16 + grp;
            const int r1 = r0 + 8;
            #pragma unroll
            for (int nt = 0; nt < 7; nt++) {
                const int j = nbase + nt * 8 + q2;
                const int kidx = sub * KH + j;
                float2 w0 = __half22float2(*(const __half2*)&g_wf[(c0 + r0) * WPITCH + kidx]);
                float2 w1 = __half22float2(*(const __half2*)&g_wf[(c0 + r1) * WPITCH + kidx]);
                __half2 h0 = __floats2half2_rn(acc[mt][nt][0] * w0.x, acc[mt][nt][1] * w0.y);
                __half2 h1 = __floats2half2_rn(acc[mt][nt][2] * w1.x, acc[mt][nt][3] * w1.y);
                *(uint32_t*)(Pa + sub * TOFF + r0 * TPITCHB + j * 2) = *(uint32_t*)&h0;
                *(uint32_t*)(Pa + sub * TOFF + r1 * TPITCHB + j * 2) = *(uint32_t*)&h1;
            }
        }
        __syncthreads();

        #pragma unroll
        for (int mt = 0; mt < 2; mt++)
            #pragma unroll
            for (int nt = 0; nt < 7; nt++)
                #pragma unroll
                for (int j = 0; j < 4; j++) acc[mt][nt][j] = 0.f;

        // ---- GEMM2: Y(e|o)[c][n] = T(e|o) x B1(e|o)^T ----
        {
            const uint32_t aB  = sPa + (uint32_t)(sub * TOFF) +
                                 (uint32_t)((cw + lr) * TPITCHB) + (uint32_t)(lc * 16);
            const uint32_t bB  = sBm + (uint32_t)((nbase + kk) * BPITCHB) + (uint32_t)(g8 * 2);
            const uint32_t bB2 = sBm + (uint32_t)((nbase + 48 + (lane & 7)) * BPITCHB) +
                                 (uint32_t)(g8 * 2);
            #pragma unroll 1
            for (int ks = 0; ks < KSTEPS; ks++) {
                const uint32_t ko = (uint32_t)(ks * 32);
                uint32_t a[2][4];
                #pragma unroll
                for (int mt = 0; mt < 2; mt++)
                    ldsm_x4(aB + (uint32_t)(mt * 16 * TPITCHB) + ko,
                            a[mt][0], a[mt][1], a[mt][2], a[mt][3]);
                uint32_t bf[7][2];
                #pragma unroll
                for (int p = 0; p < 3; p++)
                    ldsm_x4(bB + (uint32_t)(p * 16 * BPITCHB) + ko,
                            bf[2 * p][0], bf[2 * p][1], bf[2 * p + 1][0], bf[2 * p + 1][1]);
                ldsm_x2(bB2 + ko, bf[6][0], bf[6][1]);
                #pragma unroll
                for (int mt = 0; mt < 2; mt++)
                    #pragma unroll
                    for (int nt = 0; nt < 7; nt++)
                        mma16816(acc[mt][nt], a[mt][0], a[mt][1], a[mt][2], a[mt][3],
                                 bf[nt][0], bf[nt][1]);
            }
        }
        __syncthreads();   // all T reads done before Ye/Yo overwrite

        // ---- write Ye/Yo fp16 over T region ----
        #pragma unroll
        for (int mt = 0; mt < 2; mt++) {
            const int r0 = cw + mt * 16 + grp;
            const int r1 = r0 + 8;
            #pragma unroll
            for (int nt = 0; nt < 7; nt++) {
                const int n = nbase + nt * 8 + q2;
                __half2 h0 = __floats2half2_rn(acc[mt][nt][0], acc[mt][nt][1]);
                __half2 h1 = __floats2half2_rn(acc[mt][nt][2], acc[mt][nt][3]);
                *(uint32_t*)(Pa + sub * TOFF + r0 * TPITCHB + n * 2) = *(uint32_t*)&h0;
                *(uint32_t*)(Pa + sub * TOFF + r1 * TPITCHB + n * 2) = *(uint32_t*)&h1;
            }
        }
        __syncthreads();

        // ---- combine: y[n] = ye+yo, y[195-n] = ye-yo (coalesced fp32 stores) ----
        {
            float* yb = y + (size_t)b * NREAL * CDIM + c0;
            for (int i = tid; i < 49 * 128; i += NTHREADS) {
                int np = i >> 7, c = i & 127;
                int n0 = np * 2;
                uint32_t ue = *(uint32_t*)(Pa + c * TPITCHB + n0 * 2);
                uint32_t uo = *(uint32_t*)(Pa + TOFF + c * TPITCHB + n0 * 2);
                float2 fe = __half22float2(*(__half2*)&ue);
                float2 fo = __half22float2(*(__half2*)&uo);
                yb[(size_t)n0 * CDIM + c]                  = fe.x + fo.x;
                yb[(size_t)(n0 + 1) * CDIM + c]            = fe.y + fo.y;
                yb[(size_t)(NREAL - 1 - n0) * CDIM + c]    = fe.x - fo.x;
                yb[(size_t)(NREAL - 2 - n0) * CDIM + c]    = fe.y - fo.y;
            }
        }
        __syncthreads();   // Pa free for reuse as next prefetch target
    }
}

extern "C" void kernel_launch(void* const* d_in, const int* in_sizes, int n_in,
                              void* d_out, int out_size) {
    const float* x = (const float*)d_in[0];  // [B, N, C] fp32
    const float* w = (const float*)d_in[1];  // [C, N]    fp32
    float* y = (float*)d_out;                // [B, N, C] fp32

    cudaFuncSetAttribute(dct_mma_kernel,
                         cudaFuncAttributeMaxDynamicSharedMemorySize, SMEM_TOTAL);

    setup_all<<<CDIM, 240>>>(w);
    dct_mma_kernel<<<GRID, NTHREADS, SMEM_TOTAL>>>(x, y);
}